// round 10
// baseline (speedup 1.0000x reference)
#include <cuda_runtime.h>

#define VOCAB  200000
#define DIM    128
#define NPOS   10
#define NNEG   64
#define NCTX   (NPOS + NNEG)       // 74
#define NROWS  (1 + NPOS + NNEG)   // 75
#define VEC_PER_ROW (VOCAB / 4)    // 50000 float4 per row

#define THREADS 256
#define LOADS   8                  // batched consumer-free loads per iteration
#define ITERS   4                  // iterations per block
#define STRIDE  (THREADS * LOADS)  // 2048 float4 per iteration
#define COVER   (STRIDE * ITERS)   // 8192 float4 per block

#define CENTER_VEC (VEC_PER_ROW)            // 12500
#define POS_VEC    (NPOS * VEC_PER_ROW)     // 500000
#define NEG_VEC    (NNEG * VEC_PER_ROW)     // 3200000
#define CB ((CENTER_VEC + COVER - 1) / COVER)   // 2
#define PB ((POS_VEC    + COVER - 1) / COVER)   // 62
#define NB ((NEG_VEC    + COVER - 1) / COVER)   // 391
#define GRID (CB + PB + NB)                     // 455  (single wave)

// Scratch (alloc-free rule: __device__ globals).
__device__ int g_idx[NROWS];
__device__ unsigned int g_count = 0;

// Numerically stable log_sigmoid(x) = -softplus(-x)
__device__ __forceinline__ float log_sigmoidf(float x) {
    return (x >= 0.0f) ? -log1pf(expf(-x)) : (x - log1pf(expf(x)));
}

__device__ __forceinline__ bool hit_test(float4 v4, int i, int row_base) {
    // one-hot data is exactly 0.0f / 1.0f -> bitwise test is safe & cheap
    uint4 u = *reinterpret_cast<uint4*>(&v4);
    if ((u.x | u.y | u.z | u.w) != 0u) {            // rare path
        int row = i / VEC_PER_ROW;                  // const-div -> mul
        int vv  = i - row * VEC_PER_ROW;
        int sub = (u.x != 0u) ? 0 : (u.y != 0u) ? 1 : (u.z != 0u) ? 2 : 3;
        g_idx[row_base + row] = 4 * vv + sub;
        return true;
    }
    return false;
}

// ---------------------------------------------------------------------------
// Fused kernel, single-wave:
//  Phase 1: each block streams a contiguous 8192-float4 chunk of ONE array as
//   4 iterations of the proven branch-free MLP-8 batch (8 consumer-free
//   __ldcs loads -> scan). Grid = 455 -> one wave: the once-per-block
//   handshake is paid once per SM slot, in parallel across the chip.
//  Phase 2: last block scores inline and stores the scalar.
// ---------------------------------------------------------------------------
__global__ void skipgram_fused(const float4* __restrict__ center,
                               const float4* __restrict__ pos,
                               const float4* __restrict__ neg,
                               const float*  __restrict__ inE,   // [DIM, VOCAB]
                               const float*  __restrict__ outE,  // [VOCAB, DIM]
                               float* __restrict__ out) {
    const int tid = threadIdx.x;
    const int b   = blockIdx.x;

    // ---- Phase 1: streaming index recovery --------------------------------
    bool wrote = false;
    {
        const float4* base;
        int nvec, row_base, lb;
        if (b < CB)           { base = center; nvec = CENTER_VEC; row_base = 0;        lb = b; }
        else if (b < CB + PB) { base = pos;    nvec = POS_VEC;    row_base = 1;        lb = b - CB; }
        else                  { base = neg;    nvec = NEG_VEC;    row_base = 1 + NPOS; lb = b - CB - PB; }

        const int seg = lb * COVER;

        #pragma unroll
        for (int it = 0; it < ITERS; it++) {
            const int it_seg = seg + it * STRIDE;
            const int off    = it_seg + tid;
            if (it_seg + STRIDE <= nvec) {
                // fast path: branch-free batched loads (MLP=8)
                float4 x[LOADS];
                #pragma unroll
                for (int k = 0; k < LOADS; k++)
                    x[k] = __ldcs(base + off + k * THREADS);
                #pragma unroll
                for (int k = 0; k < LOADS; k++)
                    wrote |= hit_test(x[k], off + k * THREADS, row_base);
            } else {
                // boundary: checked loads
                #pragma unroll
                for (int k = 0; k < LOADS; k++) {
                    int i = off + k * THREADS;
                    if (i < nvec) wrote |= hit_test(__ldcs(base + i), i, row_base);
                }
            }
        }
    }

    // ---- Completion handshake (once per block; one wave => once per slot) --
    if (wrote) __threadfence();          // release (rare: <=75 threads total)
    __shared__ bool is_last;
    __syncthreads();                     // orders writer fences before atomic
    if (tid == 0) {
        unsigned int old = atomicAdd(&g_count, 1u);
        is_last = (old == (unsigned)(GRID - 1));
    }
    __syncthreads();
    if (!is_last) return;
    __threadfence();                     // acquire: see all g_idx stores

    // ---- Phase 2: scoring (one block, 8 warps, batched gathers) -----------
    __shared__ int   idx_s[NROWS];
    __shared__ float v[DIM];
    __shared__ float warp_acc[8];

    const int wid  = tid >> 5;
    const int lane = tid & 31;

    if (tid < NROWS) idx_s[tid] = g_idx[tid];
    __syncthreads();

    const int c = idx_s[0];
    if (tid < DIM) v[tid] = inE[(long)tid * VOCAB + c];
    __syncthreads();

    float acc = 0.0f;
    #pragma unroll
    for (int r = 0; r < 10; r++) {
        int w = wid + r * 8;             // 0..79
        if (w < NCTX) {
            const int idx = idx_s[1 + w];
            float dot = 0.0f;
            if (w < NPOS) {
                #pragma unroll
                for (int j = 0; j < DIM / 32; j++) {
                    int d = lane + 32 * j;
                    dot += v[d] * __ldg(&inE[(long)d * VOCAB + idx]);
                }
            } else {
                const float* rrow = outE + (long)idx * DIM;
                #pragma unroll
                for (int j = 0; j < DIM / 32; j++) {
                    int d = lane + 32 * j;
                    dot += v[d] * __ldg(&rrow[d]);
                }
            }
            #pragma unroll
            for (int s = 16; s; s >>= 1)
                dot += __shfl_xor_sync(0xFFFFFFFFu, dot, s);
            if (lane == 0) acc += log_sigmoidf((w < NPOS) ? dot : -dot);
        }
    }
    if (lane == 0) warp_acc[wid] = acc;
    __syncthreads();

    if (tid == 0) {
        float s = 0.0f;
        #pragma unroll
        for (int i = 0; i < 8; i++) s += warp_acc[i];
        *out = -s;
        g_count = 0;   // reset for next graph replay (deterministic)
    }
}

extern "C" void kernel_launch(void* const* d_in, const int* in_sizes, int n_in,
                              void* d_out, int out_size) {
    const float* center = (const float*)d_in[0];   // [VOCAB]
    const float* pos    = (const float*)d_in[1];   // [NPOS, VOCAB]
    const float* neg    = (const float*)d_in[2];   // [NNEG, VOCAB]
    const float* inE    = (const float*)d_in[3];   // [DIM, VOCAB]
    const float* outE   = (const float*)d_in[4];   // [VOCAB, DIM]
    float* out = (float*)d_out;

    skipgram_fused<<<GRID, THREADS>>>((const float4*)center,
                                      (const float4*)pos,
                                      (const float4*)neg,
                                      inE, outE, out);
}

// round 11
// speedup vs baseline: 1.3761x; 1.3761x over previous
#include <cuda_runtime.h>

#define VOCAB  200000
#define DIM    128
#define NPOS   10
#define NNEG   64
#define NCTX   (NPOS + NNEG)       // 74
#define NROWS  (1 + NPOS + NNEG)   // 75
#define VEC_PER_ROW (VOCAB / 4)    // 50000 float4 per row

#define THREADS 256
#define LOADS   8
#define COVER   (THREADS * LOADS)  // 2048 float4 per block

#define CENTER_VEC (VEC_PER_ROW)            // 12500
#define POS_VEC    (NPOS * VEC_PER_ROW)     // 500000
#define NEG_VEC    (NNEG * VEC_PER_ROW)     // 3200000
#define CB ((CENTER_VEC + COVER - 1) / COVER)   // 7
#define PB ((POS_VEC    + COVER - 1) / COVER)   // 245
#define NB ((NEG_VEC    + COVER - 1) / COVER)   // 1563
#define GRID_A (CB + PB + NB)                   // 1815

// Scratch (alloc-free rule: __device__ global).
__device__ int g_idx[NROWS];

// Numerically stable log_sigmoid(x) = -softplus(-x)
__device__ __forceinline__ float log_sigmoidf(float x) {
    return (x >= 0.0f) ? -log1pf(expf(-x)) : (x - log1pf(expf(x)));
}

__device__ __forceinline__ bool hit_test(float4 v4, int i, int row_base) {
    // one-hot data is exactly 0.0f / 1.0f -> bitwise test is safe & cheap
    uint4 u = *reinterpret_cast<uint4*>(&v4);
    if ((u.x | u.y | u.z | u.w) != 0u) {            // rare path
        int row = i / VEC_PER_ROW;                  // const-div -> mul
        int vv  = i - row * VEC_PER_ROW;
        int sub = (u.x != 0u) ? 0 : (u.y != 0u) ? 1 : (u.z != 0u) ? 2 : 3;
        g_idx[row_base + row] = 4 * vv + sub;
        return true;
    }
    return false;
}

// ---------------------------------------------------------------------------
// Kernel A (R7's proven body): stream 60 MB; branch-free batched __ldcs loads
// (structural MLP=8). Writer threads release-fence, then every thread signals
// PDL completion so kernel B's blocks can proceed immediately.
// ---------------------------------------------------------------------------
__global__ void skipgram_find_idx(const float4* __restrict__ center,
                                  const float4* __restrict__ pos,
                                  const float4* __restrict__ neg,
                                  float* __restrict__ out) {
    const int tid = threadIdx.x;
    const int b   = blockIdx.x;
    if (b == 0 && tid == 0) *out = 0.0f;

    const float4* base;
    int nvec, row_base, lb;
    if (b < CB)           { base = center; nvec = CENTER_VEC; row_base = 0;        lb = b; }
    else if (b < CB + PB) { base = pos;    nvec = POS_VEC;    row_base = 1;        lb = b - CB; }
    else                  { base = neg;    nvec = NEG_VEC;    row_base = 1 + NPOS; lb = b - CB - PB; }

    const int seg = lb * COVER;
    const int off = seg + tid;

    bool wrote = false;
    if (seg + COVER <= nvec) {
        // fast path: branch-free batched loads (MLP=8)
        float4 x[LOADS];
        #pragma unroll
        for (int k = 0; k < LOADS; k++)
            x[k] = __ldcs(base + off + k * THREADS);
        #pragma unroll
        for (int k = 0; k < LOADS; k++)
            wrote |= hit_test(x[k], off + k * THREADS, row_base);
    } else {
        // boundary block: checked loads
        #pragma unroll
        for (int k = 0; k < LOADS; k++) {
            int i = off + k * THREADS;
            if (i < nvec) wrote |= hit_test(__ldcs(base + i), i, row_base);
        }
    }

    // Release our g_idx store (rare: <=75 threads grid-wide), then signal PDL.
    if (wrote) __threadfence();
    cudaTriggerProgrammaticLaunchCompletion();
}

// ---------------------------------------------------------------------------
// Kernel B: 74 blocks x 128 threads, launched with PDL so blocks are resident
// and waiting while A drains. One word per block; indices L2-hot.
// ---------------------------------------------------------------------------
__global__ void skipgram_score(const float* __restrict__ inE,   // [DIM, VOCAB]
                               const float* __restrict__ outE,  // [VOCAB, DIM]
                               float* __restrict__ out) {
    cudaGridDependencySynchronize();   // wait for A's triggers (acquire)

    __shared__ float partial[4];

    const int w    = blockIdx.x;          // 0..73
    const int d    = threadIdx.x;         // 0..127
    const int wid  = d >> 5;
    const int lane = d & 31;

    const int c   = __ldg(&g_idx[0]);
    const int idx = __ldg(&g_idx[1 + w]);

    const float vd = inE[(long)d * VOCAB + c];
    const float ud = (w < NPOS) ? inE[(long)d * VOCAB + idx]
                                : outE[(long)idx * DIM + d];

    float dot = vd * ud;
    #pragma unroll
    for (int s = 16; s; s >>= 1) dot += __shfl_xor_sync(0xFFFFFFFFu, dot, s);
    if (lane == 0) partial[wid] = dot;
    __syncthreads();

    if (d == 0) {
        float t = partial[0] + partial[1] + partial[2] + partial[3];
        float x = (w < NPOS) ? t : -t;
        atomicAdd(out, -log_sigmoidf(x));
    }
}

extern "C" void kernel_launch(void* const* d_in, const int* in_sizes, int n_in,
                              void* d_out, int out_size) {
    const float* center = (const float*)d_in[0];   // [VOCAB]
    const float* pos    = (const float*)d_in[1];   // [NPOS, VOCAB]
    const float* neg    = (const float*)d_in[2];   // [NNEG, VOCAB]
    const float* inE    = (const float*)d_in[3];   // [DIM, VOCAB]
    const float* outE   = (const float*)d_in[4];   // [VOCAB, DIM]
    float* out = (float*)d_out;

    skipgram_find_idx<<<GRID_A, THREADS>>>((const float4*)center,
                                           (const float4*)pos,
                                           (const float4*)neg, out);

    // Kernel B with Programmatic Dependent Launch: blocks launch while A
    // drains, spin in cudaGridDependencySynchronize, proceed on trigger.
    cudaLaunchConfig_t cfg = {};
    cfg.gridDim  = dim3(NCTX);
    cfg.blockDim = dim3(DIM);
    cfg.dynamicSmemBytes = 0;
    cfg.stream = 0;
    cudaLaunchAttribute attr[1];
    attr[0].id = cudaLaunchAttributeProgrammaticStreamSerialization;
    attr[0].val.programmaticStreamSerializationAllowed = 1;
    cfg.attrs = attr;
    cfg.numAttrs = 1;
    cudaLaunchKernelEx(&cfg, skipgram_score, inE, outE, out);
}